// round 2
// baseline (speedup 1.0000x reference)
#include <cuda_runtime.h>

#define BB   16
#define CIN  1024
#define HH   32
#define WW   32
#define HW   1024
#define CK   256
#define CV   512
#define KTOT (CIN * 9)   // 9216

// ---------------- scratch (no allocs allowed) ----------------
__device__ float g_mkey[BB * CK * HW];              // 16.8 MB
__device__ float g_mval[BB * CV * HW];              // 33.6 MB
__device__ float g_qkey[BB * CK * HW];              // 16.8 MB
__device__ float g_scores[(size_t)BB * HW * HW];    // 67.1 MB

// =====================================================================
// Conv3x3 as implicit GEMM: out[co][n] = sum_k W[co][k] * X[k][n]
//   k = ci*9 + tap, n = y*32+x, X[k][n] = x[ci][y+dy][x+dx] (0-padded)
// Tile 128x128, KB=8, 256 threads, 8x8 microtile.
// mt<2 -> key conv (C_out=256), mt>=2 -> value conv (C_out=512).
// =====================================================================
__global__ __launch_bounds__(256, 2) void conv_kernel(
    const float* __restrict__ x,
    const float* __restrict__ wk, const float* __restrict__ bk,
    const float* __restrict__ wv, const float* __restrict__ bv,
    float* __restrict__ outk,
    float* __restrict__ outv, int outv_bstride)
{
    __shared__ float As[8][128];   // [k][m]
    __shared__ float Bs[8][128];   // [k][n]

    const int b  = blockIdx.z;
    const int mt = blockIdx.y;
    const int n0 = blockIdx.x * 128;

    const float* wght; const float* bias; float* outp; int co0;
    if (mt < 2) { wght = wk; bias = bk; co0 = mt * 128;
                  outp = outk + (size_t)b * CK * HW; }
    else        { wght = wv; bias = bv; co0 = (mt - 2) * 128;
                  outp = outv + (size_t)b * outv_bstride; }

    const float* xb = x + (size_t)b * CIN * HW;

    const int tid = threadIdx.x;
    const int am  = tid >> 1;            // 0..127  (A row = co)
    const int ak  = (tid & 1) << 2;      // 0 or 4
    const int bkk = tid >> 5;            // 0..7    (B row = k)
    const int bn  = (tid & 31) << 2;     // 0..124
    const int tx  = tid & 15, ty = tid >> 4;

    float acc[8][8];
    #pragma unroll
    for (int i = 0; i < 8; i++)
        #pragma unroll
        for (int j = 0; j < 8; j++) acc[i][j] = 0.f;

    const float* aptr = wght + (size_t)(co0 + am) * KTOT + ak;

    for (int k0 = 0; k0 < KTOT; k0 += 8) {
        // ---- stage A (weights, contiguous) ----
        float4 av = *reinterpret_cast<const float4*>(aptr + k0);
        // ---- stage B (shifted input gather) ----
        const int k   = k0 + bkk;
        const int ci  = k / 9;
        const int tap = k - ci * 9;
        const int t3  = tap / 3;
        const int dy  = t3 - 1;
        const int dx  = tap - t3 * 3 - 1;
        const float* xc = xb + ci * HW;
        float bg[4];
        #pragma unroll
        for (int j = 0; j < 4; j++) {
            const int n  = n0 + bn + j;
            const int yy = (n >> 5) + dy;
            const int xx = (n & 31) + dx;
            bg[j] = (yy >= 0 && yy < HH && xx >= 0 && xx < WW)
                        ? xc[yy * WW + xx] : 0.f;
        }
        __syncthreads();
        As[ak + 0][am] = av.x; As[ak + 1][am] = av.y;
        As[ak + 2][am] = av.z; As[ak + 3][am] = av.w;
        *reinterpret_cast<float4*>(&Bs[bkk][bn]) =
            make_float4(bg[0], bg[1], bg[2], bg[3]);
        __syncthreads();

        #pragma unroll
        for (int kk = 0; kk < 8; kk++) {
            float a[8], bv8[8];
            *(float4*)&a[0]   = *(const float4*)&As[kk][ty << 2];
            *(float4*)&a[4]   = *(const float4*)&As[kk][64 + (ty << 2)];
            *(float4*)&bv8[0] = *(const float4*)&Bs[kk][tx << 2];
            *(float4*)&bv8[4] = *(const float4*)&Bs[kk][64 + (tx << 2)];
            #pragma unroll
            for (int i = 0; i < 8; i++)
                #pragma unroll
                for (int j = 0; j < 8; j++)
                    acc[i][j] = fmaf(a[i], bv8[j], acc[i][j]);
        }
    }

    #pragma unroll
    for (int i = 0; i < 8; i++) {
        const int mr = (i < 4) ? ((ty << 2) + i) : (64 + (ty << 2) + i - 4);
        const int m  = co0 + mr;
        const float bia = bias[m];
        float* op = outp + (size_t)m * HW + n0;
        float4 v0 = make_float4(acc[i][0] + bia, acc[i][1] + bia,
                                acc[i][2] + bia, acc[i][3] + bia);
        float4 v1 = make_float4(acc[i][4] + bia, acc[i][5] + bia,
                                acc[i][6] + bia, acc[i][7] + bia);
        *reinterpret_cast<float4*>(op + (tx << 2))      = v0;
        *reinterpret_cast<float4*>(op + 64 + (tx << 2)) = v1;
    }
}

// =====================================================================
// Scores: S[b][q][m] = (1/16) * sum_c qk[b][c][q] * mk[b][c][m]
// Both operands are k-major in memory -> direct coalesced tile loads.
// =====================================================================
__global__ __launch_bounds__(256, 2) void scores_kernel(
    const float* __restrict__ qkey, const float* __restrict__ mkey,
    float* __restrict__ S)
{
    __shared__ float As[8][128];   // [c][q]
    __shared__ float Bs[8][128];   // [c][m]
    const int b  = blockIdx.z;
    const int q0 = blockIdx.y * 128;
    const int m0 = blockIdx.x * 128;
    const float* qk = qkey + (size_t)b * CK * HW;
    const float* mk = mkey + (size_t)b * CK * HW;

    const int tid = threadIdx.x;
    const int kk  = tid >> 5;
    const int col = (tid & 31) << 2;
    const int tx  = tid & 15, ty = tid >> 4;

    float acc[8][8];
    #pragma unroll
    for (int i = 0; i < 8; i++)
        #pragma unroll
        for (int j = 0; j < 8; j++) acc[i][j] = 0.f;

    for (int c0 = 0; c0 < CK; c0 += 8) {
        float4 aq = *(const float4*)(qk + (size_t)(c0 + kk) * HW + q0 + col);
        float4 bm = *(const float4*)(mk + (size_t)(c0 + kk) * HW + m0 + col);
        __syncthreads();
        *(float4*)&As[kk][col] = aq;
        *(float4*)&Bs[kk][col] = bm;
        __syncthreads();
        #pragma unroll
        for (int k2 = 0; k2 < 8; k2++) {
            float a[8], bv8[8];
            *(float4*)&a[0]   = *(const float4*)&As[k2][ty << 2];
            *(float4*)&a[4]   = *(const float4*)&As[k2][64 + (ty << 2)];
            *(float4*)&bv8[0] = *(const float4*)&Bs[k2][tx << 2];
            *(float4*)&bv8[4] = *(const float4*)&Bs[k2][64 + (tx << 2)];
            #pragma unroll
            for (int i = 0; i < 8; i++)
                #pragma unroll
                for (int j = 0; j < 8; j++)
                    acc[i][j] = fmaf(a[i], bv8[j], acc[i][j]);
        }
    }

    float* Sb = S + (size_t)b * HW * HW;
    #pragma unroll
    for (int i = 0; i < 8; i++) {
        const int qr = (i < 4) ? ((ty << 2) + i) : (64 + (ty << 2) + i - 4);
        float* op = Sb + (size_t)(q0 + qr) * HW + m0;
        float4 v0 = make_float4(acc[i][0] * 0.0625f, acc[i][1] * 0.0625f,
                                acc[i][2] * 0.0625f, acc[i][3] * 0.0625f);
        float4 v1 = make_float4(acc[i][4] * 0.0625f, acc[i][5] * 0.0625f,
                                acc[i][6] * 0.0625f, acc[i][7] * 0.0625f);
        *reinterpret_cast<float4*>(op + (tx << 2))      = v0;
        *reinterpret_cast<float4*>(op + 64 + (tx << 2)) = v1;
    }
}

// =====================================================================
// Softmax over the contiguous last axis (m) of S[b][q][m], in place.
// One block per (b,q) row, 256 threads x 4 elems.
// =====================================================================
__global__ __launch_bounds__(256) void softmax_kernel(float* __restrict__ S)
{
    __shared__ float red[8];
    float* row = S + (size_t)blockIdx.x * HW;
    const int tid = threadIdx.x;

    float4 v = *reinterpret_cast<const float4*>(row + (tid << 2));
    float mx = fmaxf(fmaxf(v.x, v.y), fmaxf(v.z, v.w));
    #pragma unroll
    for (int o = 16; o; o >>= 1)
        mx = fmaxf(mx, __shfl_xor_sync(0xffffffffu, mx, o));
    if ((tid & 31) == 0) red[tid >> 5] = mx;
    __syncthreads();
    mx = red[0];
    #pragma unroll
    for (int w = 1; w < 8; w++) mx = fmaxf(mx, red[w]);
    __syncthreads();

    float e0 = __expf(v.x - mx), e1 = __expf(v.y - mx);
    float e2 = __expf(v.z - mx), e3 = __expf(v.w - mx);
    float s = (e0 + e1) + (e2 + e3);
    #pragma unroll
    for (int o = 16; o; o >>= 1)
        s += __shfl_xor_sync(0xffffffffu, s, o);
    if ((tid & 31) == 0) red[tid >> 5] = s;
    __syncthreads();
    float tot = red[0];
    #pragma unroll
    for (int w = 1; w < 8; w++) tot += red[w];
    const float inv = 1.f / tot;

    *reinterpret_cast<float4*>(row + (tid << 2)) =
        make_float4(e0 * inv, e1 * inv, e2 * inv, e3 * inv);
}

// =====================================================================
// mem_info: O[b][c][q] = sum_m mv[b][c][m] * S[b][q][m]
// Both operands row-major along k=m -> transpose on smem fill.
// Writes directly into d_out channels [0,512).
// =====================================================================
__global__ __launch_bounds__(256, 2) void outv_kernel(
    const float* __restrict__ mval, const float* __restrict__ S,
    float* __restrict__ out)
{
    __shared__ float As[8][128];   // [m][c]
    __shared__ float Bs[8][128];   // [m][q]
    const int b  = blockIdx.z;
    const int c0 = blockIdx.y * 128;
    const int q0 = blockIdx.x * 128;
    const float* A  = mval + (size_t)b * CV * HW;   // [c][m]
    const float* Bm = S    + (size_t)b * HW * HW;   // [q][m]

    const int tid = threadIdx.x;
    const int ar = tid >> 1;            // row within tile (c or q)
    const int a4 = (tid & 1) << 2;      // k offset
    const int tx = tid & 15, ty = tid >> 4;

    float acc[8][8];
    #pragma unroll
    for (int i = 0; i < 8; i++)
        #pragma unroll
        for (int j = 0; j < 8; j++) acc[i][j] = 0.f;

    for (int k0 = 0; k0 < HW; k0 += 8) {
        float4 av = *(const float4*)(A  + (size_t)(c0 + ar) * HW + k0 + a4);
        float4 bq = *(const float4*)(Bm + (size_t)(q0 + ar) * HW + k0 + a4);
        __syncthreads();
        As[a4 + 0][ar] = av.x; As[a4 + 1][ar] = av.y;
        As[a4 + 2][ar] = av.z; As[a4 + 3][ar] = av.w;
        Bs[a4 + 0][ar] = bq.x; Bs[a4 + 1][ar] = bq.y;
        Bs[a4 + 2][ar] = bq.z; Bs[a4 + 3][ar] = bq.w;
        __syncthreads();
        #pragma unroll
        for (int kk = 0; kk < 8; kk++) {
            float a[8], bv8[8];
            *(float4*)&a[0]   = *(const float4*)&As[kk][ty << 2];
            *(float4*)&a[4]   = *(const float4*)&As[kk][64 + (ty << 2)];
            *(float4*)&bv8[0] = *(const float4*)&Bs[kk][tx << 2];
            *(float4*)&bv8[4] = *(const float4*)&Bs[kk][64 + (tx << 2)];
            #pragma unroll
            for (int i = 0; i < 8; i++)
                #pragma unroll
                for (int j = 0; j < 8; j++)
                    acc[i][j] = fmaf(a[i], bv8[j], acc[i][j]);
        }
    }

    float* ob = out + (size_t)b * 1024 * HW;   // full output: 1024 channels
    #pragma unroll
    for (int i = 0; i < 8; i++) {
        const int cr = (i < 4) ? ((ty << 2) + i) : (64 + (ty << 2) + i - 4);
        float* op = ob + (size_t)(c0 + cr) * HW + q0;
        *reinterpret_cast<float4*>(op + (tx << 2)) =
            make_float4(acc[i][0], acc[i][1], acc[i][2], acc[i][3]);
        *reinterpret_cast<float4*>(op + 64 + (tx << 2)) =
            make_float4(acc[i][4], acc[i][5], acc[i][6], acc[i][7]);
    }
}

// =====================================================================
extern "C" void kernel_launch(void* const* d_in, const int* in_sizes, int n_in,
                              void* d_out, int out_size)
{
    const float* src_temp   = (const float*)d_in[0];
    const float* src_search = (const float*)d_in[1];
    const float* wk_m = (const float*)d_in[2];
    const float* bk_m = (const float*)d_in[3];
    const float* wv_m = (const float*)d_in[4];
    const float* bv_m = (const float*)d_in[5];
    const float* wk_q = (const float*)d_in[6];
    const float* bk_q = (const float*)d_in[7];
    const float* wv_q = (const float*)d_in[8];
    const float* bv_q = (const float*)d_in[9];
    float* out = (float*)d_out;

    float *mkey, *mval, *qkey, *scores;
    cudaGetSymbolAddress((void**)&mkey,   g_mkey);
    cudaGetSymbolAddress((void**)&mval,   g_mval);
    cudaGetSymbolAddress((void**)&qkey,   g_qkey);
    cudaGetSymbolAddress((void**)&scores, g_scores);

    dim3 blk(256);

    // convs: 6 m-tiles = 2 (key, 256ch) + 4 (value, 512ch)
    dim3 gconv(HW / 128, 6, BB);
    conv_kernel<<<gconv, blk>>>(src_temp, wk_m, bk_m, wv_m, bv_m,
                                mkey, mval, CV * HW);
    // q_value goes straight into d_out channels [512,1024)
    conv_kernel<<<gconv, blk>>>(src_search, wk_q, bk_q, wv_q, bv_q,
                                qkey, out + (size_t)CV * HW, 1024 * HW);

    dim3 gsc(HW / 128, HW / 128, BB);
    scores_kernel<<<gsc, blk>>>(qkey, mkey, scores);

    softmax_kernel<<<BB * HW, 256>>>(scores);

    dim3 gov(HW / 128, CV / 128, BB);
    outv_kernel<<<gov, blk>>>(mval, scores, out);
}

// round 5
// speedup vs baseline: 2.0600x; 2.0600x over previous
#include <cuda_runtime.h>
#include <cuda_bf16.h>
#include <cstdint>

#define BB   16
#define CIN  1024
#define HH   32
#define WW   32
#define HW   1024
#define CK   256
#define CV   512
#define KTOT 9216
#define NCH  288          // K chunks of 32

// ---------------- scratch (no allocs allowed) ----------------
__device__ float g_mkey[BB * CK * HW];              // 16.8 MB
__device__ float g_mval[BB * CV * HW];              // 33.6 MB
__device__ float g_qkey[BB * CK * HW];              // 16.8 MB
__device__ float g_scores[(size_t)BB * HW * HW];    // 67.1 MB
// bf16 hi/lo planes: input NHWC transposed [src*16+b][n][ci]
__device__ __align__(16) __nv_bfloat16 g_xh[(size_t)2 * BB * HW * CIN];
__device__ __align__(16) __nv_bfloat16 g_xl[(size_t)2 * BB * HW * CIN];
// weights packed [row 0..1535][tap*1024+ci] (wk_m,wv_m,wk_q,wv_q stacked)
__device__ __align__(16) __nv_bfloat16 g_wh[(size_t)1536 * KTOT];
__device__ __align__(16) __nv_bfloat16 g_wl[(size_t)1536 * KTOT];

// ================= helpers (baseline ISA only: sm_80-class) =================
__device__ __forceinline__ uint32_t smem_u32(const void* p) {
    uint32_t a;
    asm("{ .reg .u64 t; cvta.to.shared.u64 t, %1; cvt.u32.u64 %0, t; }"
        : "=r"(a) : "l"(p));
    return a;
}
__device__ __forceinline__ void cpasync16(uint32_t dst, const void* src, int srcbytes) {
    asm volatile("cp.async.cg.shared.global [%0], [%1], 16, %2;"
                 :: "r"(dst), "l"(src), "r"(srcbytes) : "memory");
}
#define CP_COMMIT() asm volatile("cp.async.commit_group;" ::: "memory")
#define CP_WAIT(n)  asm volatile("cp.async.wait_group %0;" :: "n"(n) : "memory")

#define LDSM4(R, addr) \
    asm volatile("ldmatrix.sync.aligned.m8n8.x4.shared.b16 {%0,%1,%2,%3}, [%4];" \
        : "=r"((R)[0]), "=r"((R)[1]), "=r"((R)[2]), "=r"((R)[3]) : "r"(addr))

#define MMA16816(C, A, b0, b1) \
    asm volatile("mma.sync.aligned.m16n8k16.row.col.f32.bf16.bf16.f32 " \
        "{%0,%1,%2,%3}, {%4,%5,%6,%7}, {%8,%9}, {%0,%1,%2,%3};" \
        : "+f"((C)[0]), "+f"((C)[1]), "+f"((C)[2]), "+f"((C)[3]) \
        : "r"((A)[0]), "r"((A)[1]), "r"((A)[2]), "r"((A)[3]), "r"(b0), "r"(b1))

// ================= prep kernels =================
__global__ __launch_bounds__(256) void prep_w_kernel(
    const float* __restrict__ wk_m, const float* __restrict__ wv_m,
    const float* __restrict__ wk_q, const float* __restrict__ wv_q,
    __nv_bfloat16* __restrict__ wh, __nv_bfloat16* __restrict__ wl)
{
    size_t idx = (size_t)blockIdx.x * 256 + threadIdx.x;   // < 1536*9216
    int row = (int)(idx / KTOT);
    int k   = (int)(idx - (size_t)row * KTOT);
    int tap = k >> 10, ci = k & 1023;
    const float* src; int co;
    if      (row < 256)  { src = wk_m; co = row; }
    else if (row < 768)  { src = wv_m; co = row - 256; }
    else if (row < 1024) { src = wk_q; co = row - 768; }
    else                 { src = wv_q; co = row - 1024; }
    float v = src[((size_t)co * CIN + ci) * 9 + tap];
    __nv_bfloat16 h = __float2bfloat16(v);
    wh[idx] = h;
    wl[idx] = __float2bfloat16(v - __bfloat162float(h));
}

__global__ __launch_bounds__(256) void prep_x_kernel(
    const float* __restrict__ xt, const float* __restrict__ xs,
    __nv_bfloat16* __restrict__ xh, __nv_bfloat16* __restrict__ xl)
{
    __shared__ float t[32][33];
    int bz = blockIdx.z;
    const float* src = (bz < BB) ? (xt + (size_t)bz * CIN * HW)
                                 : (xs + (size_t)(bz - BB) * CIN * HW);
    size_t dsto = (size_t)bz * HW * CIN;
    int ci0 = blockIdx.y * 32, n0 = blockIdx.x * 32;
    int tx = threadIdx.x & 31, ty = threadIdx.x >> 5;   // (32,8)
    #pragma unroll
    for (int i = ty; i < 32; i += 8)
        t[i][tx] = src[(size_t)(ci0 + i) * HW + n0 + tx];
    __syncthreads();
    #pragma unroll
    for (int i = ty; i < 32; i += 8) {
        float v = t[tx][i];
        __nv_bfloat16 h = __float2bfloat16(v);
        size_t o = dsto + (size_t)(n0 + i) * CIN + ci0 + tx;
        xh[o] = h;
        xl[o] = __float2bfloat16(v - __bfloat162float(h));
    }
}

// ================= mma.sync conv kernel =================
// out[co][n] = bias[co] + sum_{tap,ci} W[co][tap*1024+ci] * X[n+shift(tap)][ci]
// Block tile 128(co) x 128(n), K-chunk 32 (one tap per chunk).
// 8 warps (4 m x 2 n), warp tile 32x64, m16n8k16 bf16, 3-way err-comp split.
#define PITCH  80                 // smem row pitch bytes (32 bf16 data + pad)
#define PLANE  (128 * PITCH)      // 10240 B
#define OFF_AL PLANE
#define OFF_BH (2 * PLANE)
#define STAGE  (4 * PLANE)        // 40960 B
#define CONV_SMEM (2 * STAGE)     // 81920 B

__global__ __launch_bounds__(256, 1) void conv_mma_kernel(
    const __nv_bfloat16* __restrict__ xh, const __nv_bfloat16* __restrict__ xl,
    const __nv_bfloat16* __restrict__ wh, const __nv_bfloat16* __restrict__ wl,
    const float* __restrict__ bk, const float* __restrict__ bv,
    float* __restrict__ outk,
    float* __restrict__ outv, int outv_bstride, int wbase)
{
    extern __shared__ __align__(128) char smem[];
    const uint32_t sb = smem_u32(smem);
    const int tid = threadIdx.x, wid = tid >> 5, lid = tid & 31;
    const int b = blockIdx.z, mt = blockIdx.y, n0 = blockIdx.x * 128;

    int co0, wrow; const float* bias; float* outp;
    if (mt < 2) { co0 = mt * 128;       bias = bk; wrow = wbase + co0;
                  outp = outk + (size_t)b * CK * HW; }
    else        { co0 = (mt - 2) * 128; bias = bv; wrow = wbase + 256 + co0;
                  outp = outv + (size_t)b * outv_bstride; }

    const __nv_bfloat16* xhb = xh + (size_t)b * HW * CIN;
    const __nv_bfloat16* xlb = xl + (size_t)b * HW * CIN;

    // --- loader assignment: 256 threads -> 128 rows x 2 half-rows (32 B each)
    const int row = tid >> 1, half = tid & 1;
    const __nv_bfloat16* wha = wh + (size_t)(wrow + row) * KTOT;
    const __nv_bfloat16* wla = wl + (size_t)(wrow + row) * KTOT;
    const int nB = n0 + row, yB = nB >> 5, xB = nB & 31;
    const uint32_t dA = sb + row * PITCH + half * 32;
    const uint32_t dB = dA + OFF_BH;

    auto load = [&](int ch, int stage) {
        const uint32_t st = (uint32_t)stage * STAGE;
        const int tap = ch >> 5, ci0 = (ch & 31) * 32;
        const int ko = tap * 1024 + ci0 + half * 16;
        cpasync16(dA + st,               wha + ko,     16);
        cpasync16(dA + st + 16,          wha + ko + 8, 16);
        cpasync16(dA + st + OFF_AL,      wla + ko,     16);
        cpasync16(dA + st + OFF_AL + 16, wla + ko + 8, 16);
        const int sy = yB + tap / 3 - 1;
        const int sx = xB + tap % 3 - 1;
        const bool v = ((unsigned)sy < 32u) && ((unsigned)sx < 32u);
        const size_t so = v ? ((size_t)(sy * WW + sx) * CIN + ci0 + half * 16) : 0;
        const int sz = v ? 16 : 0;
        cpasync16(dB + st,              xhb + so,     sz);
        cpasync16(dB + st + 16,         xhb + so + 8, sz);
        cpasync16(dB + st + PLANE,      xlb + so,     sz);
        cpasync16(dB + st + PLANE + 16, xlb + so + 8, sz);
    };

    // --- warp tiling
    const int wm = wid & 3, wn = wid >> 2;
    const uint32_t aAddr = sb + (uint32_t)(wm * 32 + (lid & 15)) * PITCH + (lid >> 4) * 16;
    const uint32_t bAddr = sb + OFF_BH + (uint32_t)(wn * 64 + (lid & 15)) * PITCH + (lid >> 4) * 16;

    float acc[2][8][4];
    #pragma unroll
    for (int mb = 0; mb < 2; mb++)
        #pragma unroll
        for (int j = 0; j < 8; j++)
            #pragma unroll
            for (int q = 0; q < 4; q++) acc[mb][j][q] = 0.f;

    auto compute = [&](int stage) {
        const uint32_t st = (uint32_t)stage * STAGE;
        #pragma unroll
        for (int ks = 0; ks < 2; ks++) {
            const uint32_t kb = ks * 32;
            uint32_t Ah[2][4], Al[2][4], Bh[4][4], Bl[4][4];
            #pragma unroll
            for (int mb = 0; mb < 2; mb++) {
                LDSM4(Ah[mb], aAddr + st + mb * 16 * PITCH + kb);
                LDSM4(Al[mb], aAddr + st + OFF_AL + mb * 16 * PITCH + kb);
            }
            #pragma unroll
            for (int g = 0; g < 4; g++) {
                LDSM4(Bh[g], bAddr + st + g * 16 * PITCH + kb);
                LDSM4(Bl[g], bAddr + st + PLANE + g * 16 * PITCH + kb);
            }
            #pragma unroll
            for (int mb = 0; mb < 2; mb++)
                #pragma unroll
                for (int j = 0; j < 8; j++) {
                    const int g = j >> 1, o = j & 1;
                    const uint32_t b0h = Bh[g][o], b1h = Bh[g][o + 2];
                    const uint32_t b0l = Bl[g][o], b1l = Bl[g][o + 2];
                    MMA16816(acc[mb][j], Ah[mb], b0h, b1h);
                    MMA16816(acc[mb][j], Al[mb], b0h, b1h);
                    MMA16816(acc[mb][j], Ah[mb], b0l, b1l);
                }
        }
    };

    // --- double-buffered mainloop
    load(0, 0); CP_COMMIT();
    for (int ch = 0; ch < NCH; ch++) {
        if (ch + 1 < NCH) { load(ch + 1, (ch + 1) & 1); CP_COMMIT(); CP_WAIT(1); }
        else              { CP_WAIT(0); }
        __syncthreads();
        compute(ch & 1);
        __syncthreads();
    }

    // --- epilogue: bias + store fp32
    const int lr = lid >> 2, lc = (lid & 3) * 2;
    #pragma unroll
    for (int mb = 0; mb < 2; mb++) {
        const int m = co0 + wm * 32 + mb * 16 + lr;
        const float bia0 = bias[m], bia1 = bias[m + 8];
        float* p = outp + (size_t)m * HW + n0 + wn * 64 + lc;
        #pragma unroll
        for (int j = 0; j < 8; j++) {
            float2 v0 = make_float2(acc[mb][j][0] + bia0, acc[mb][j][1] + bia0);
            float2 v1 = make_float2(acc[mb][j][2] + bia1, acc[mb][j][3] + bia1);
            *reinterpret_cast<float2*>(p + j * 8)          = v0;
            *reinterpret_cast<float2*>(p + 8 * HW + j * 8) = v1;
        }
    }
}

// ================= SIMT attention (unchanged, proven) =================
__global__ __launch_bounds__(256, 2) void scores_kernel(
    const float* __restrict__ qkey, const float* __restrict__ mkey,
    float* __restrict__ S)
{
    __shared__ float As[8][128];
    __shared__ float Bs[8][128];
    const int b  = blockIdx.z;
    const int q0 = blockIdx.y * 128;
    const int m0 = blockIdx.x * 128;
    const float* qk = qkey + (size_t)b * CK * HW;
    const float* mk = mkey + (size_t)b * CK * HW;

    const int tid = threadIdx.x;
    const int kk  = tid >> 5;
    const int col = (tid & 31) << 2;
    const int tx  = tid & 15, ty = tid >> 4;

    float acc[8][8];
    #pragma unroll
    for (int i = 0; i < 8; i++)
        #pragma unroll
        for (int j = 0; j < 8; j++) acc[i][j] = 0.f;

    for (int c0 = 0; c0 < CK; c0 += 8) {
        float4 aq = *(const float4*)(qk + (size_t)(c0 + kk) * HW + q0 + col);
        float4 bm = *(const float4*)(mk + (size_t)(c0 + kk) * HW + m0 + col);
        __syncthreads();
        *(float4*)&As[kk][col] = aq;
        *(float4*)&Bs[kk][col] = bm;
        __syncthreads();
        #pragma unroll
        for (int k2 = 0; k2 < 8; k2++) {
            float a[8], bv8[8];
            *(float4*)&a[0]   = *(const float4*)&As[k2][ty << 2];
            *(float4*)&a[4]   = *(const float4*)&As[k2][64 + (ty << 2)];
            *(float4*)&bv8[0] = *(const float4*)&Bs[k2][tx << 2];
            *(float4*)&bv8[4] = *(const float4*)&Bs[k2][64 + (tx << 2)];
            #pragma unroll
            for (int i = 0; i < 8; i++)
                #pragma unroll
                for (int j = 0; j < 8; j++)
                    acc[i][j] = fmaf(a[i], bv8[j], acc[i][j]);
        }
    }

    float* Sb = S + (size_t)b * HW * HW;
    #pragma unroll
    for (int i = 0; i < 8; i++) {
        const int qr = (i < 4) ? ((ty << 2) + i) : (64 + (ty << 2) + i - 4);
        float* op = Sb + (size_t)(q0 + qr) * HW + m0;
        *(float4*)(op + (tx << 2)) =
            make_float4(acc[i][0] * 0.0625f, acc[i][1] * 0.0625f,
                        acc[i][2] * 0.0625f, acc[i][3] * 0.0625f);
        *(float4*)(op + 64 + (tx << 2)) =
            make_float4(acc[i][4] * 0.0625f, acc[i][5] * 0.0625f,
                        acc[i][6] * 0.0625f, acc[i][7] * 0.0625f);
    }
}

__global__ __launch_bounds__(256) void softmax_kernel(float* __restrict__ S)
{
    __shared__ float red[8];
    float* row = S + (size_t)blockIdx.x * HW;
    const int tid = threadIdx.x;

    float4 v = *reinterpret_cast<const float4*>(row + (tid << 2));
    float mx = fmaxf(fmaxf(v.x, v.y), fmaxf(v.z, v.w));
    #pragma unroll
    for (int o = 16; o; o >>= 1)
        mx = fmaxf(mx, __shfl_xor_sync(0xffffffffu, mx, o));
    if ((tid & 31) == 0) red[tid >> 5] = mx;
    __syncthreads();
    mx = red[0];
    #pragma unroll
    for (int w = 1; w < 8; w++) mx = fmaxf(mx, red[w]);
    __syncthreads();

    float e0 = __expf(v.x - mx), e1 = __expf(v.y - mx);
    float e2 = __expf(v.z - mx), e3 = __expf(v.w - mx);
    float s = (e0 + e1) + (e2 + e3);
    #pragma unroll
    for (int o = 16; o; o >>= 1)
        s += __shfl_xor_sync(0xffffffffu, s, o);
    if ((tid & 31) == 0) red[tid >> 5] = s;
    __syncthreads();
    float tot = red[0];
    #pragma unroll
    for (int w = 1; w < 8; w++) tot += red[w];
    const float inv = 1.f / tot;

    *reinterpret_cast<float4*>(row + (tid << 2)) =
        make_float4(e0 * inv, e1 * inv, e2 * inv, e3 * inv);
}

__global__ __launch_bounds__(256, 2) void outv_kernel(
    const float* __restrict__ mval, const float* __restrict__ S,
    float* __restrict__ out)
{
    __shared__ float As[8][128];
    __shared__ float Bs[8][128];
    const int b  = blockIdx.z;
    const int c0 = blockIdx.y * 128;
    const int q0 = blockIdx.x * 128;
    const float* A  = mval + (size_t)b * CV * HW;
    const float* Bm = S    + (size_t)b * HW * HW;

    const int tid = threadIdx.x;
    const int ar = tid >> 1;
    const int a4 = (tid & 1) << 2;
    const int tx = tid & 15, ty = tid >> 4;

    float acc[8][8];
    #pragma unroll
    for (int i = 0; i < 8; i++)
        #pragma unroll
        for (int j = 0; j < 8; j++) acc[i][j] = 0.f;

    for (int k0 = 0; k0 < HW; k0 += 8) {
        float4 av = *(const float4*)(A  + (size_t)(c0 + ar) * HW + k0 + a4);
        float4 bq = *(const float4*)(Bm + (size_t)(q0 + ar) * HW + k0 + a4);
        __syncthreads();
        As[a4 + 0][ar] = av.x; As[a4 + 1][ar] = av.y;
        As[a4 + 2][ar] = av.z; As[a4 + 3][ar] = av.w;
        Bs[a4 + 0][ar] = bq.x; Bs[a4 + 1][ar] = bq.y;
        Bs[a4 + 2][ar] = bq.z; Bs[a4 + 3][ar] = bq.w;
        __syncthreads();
        #pragma unroll
        for (int kk = 0; kk < 8; kk++) {
            float a[8], bv8[8];
            *(float4*)&a[0]   = *(const float4*)&As[kk][ty << 2];
            *(float4*)&a[4]   = *(const float4*)&As[kk][64 + (ty << 2)];
            *(float4*)&bv8[0] = *(const float4*)&Bs[kk][tx << 2];
            *(float4*)&bv8[4] = *(const float4*)&Bs[kk][64 + (tx << 2)];
            #pragma unroll
            for (int i = 0; i < 8; i++)
                #pragma unroll
                for (int j = 0; j < 8; j++)
                    acc[i][j] = fmaf(a[i], bv8[j], acc[i][j]);
        }
    }

    float* ob = out + (size_t)b * 1024 * HW;
    #pragma unroll
    for (int i = 0; i < 8; i++) {
        const int cr = (i < 4) ? ((ty << 2) + i) : (64 + (ty << 2) + i - 4);
        float* op = ob + (size_t)(c0 + cr) * HW + q0;
        *(float4*)(op + (tx << 2)) =
            make_float4(acc[i][0], acc[i][1], acc[i][2], acc[i][3]);
        *(float4*)(op + 64 + (tx << 2)) =
            make_float4(acc[i][4], acc[i][5], acc[i][6], acc[i][7]);
    }
}

// =====================================================================
extern "C" void kernel_launch(void* const* d_in, const int* in_sizes, int n_in,
                              void* d_out, int out_size)
{
    const float* src_temp   = (const float*)d_in[0];
    const float* src_search = (const float*)d_in[1];
    const float* wk_m = (const float*)d_in[2];
    const float* bk_m = (const float*)d_in[3];
    const float* wv_m = (const float*)d_in[4];
    const float* bv_m = (const float*)d_in[5];
    const float* wk_q = (const float*)d_in[6];
    const float* bk_q = (const float*)d_in[7];
    const float* wv_q = (const float*)d_in[8];
    const float* bv_q = (const float*)d_in[9];
    float* out = (float*)d_out;

    float *mkey, *mval, *qkey, *scores;
    __nv_bfloat16 *xh, *xl, *wh, *wl;
    cudaGetSymbolAddress((void**)&mkey,   g_mkey);
    cudaGetSymbolAddress((void**)&mval,   g_mval);
    cudaGetSymbolAddress((void**)&qkey,   g_qkey);
    cudaGetSymbolAddress((void**)&scores, g_scores);
    cudaGetSymbolAddress((void**)&xh, g_xh);
    cudaGetSymbolAddress((void**)&xl, g_xl);
    cudaGetSymbolAddress((void**)&wh, g_wh);
    cudaGetSymbolAddress((void**)&wl, g_wl);

    cudaFuncSetAttribute(conv_mma_kernel,
                         cudaFuncAttributeMaxDynamicSharedMemorySize, CONV_SMEM);

    // ---- prep: bf16 split + layout re-pack ----
    prep_w_kernel<<<(1536 * KTOT) / 256, 256>>>(wk_m, wv_m, wk_q, wv_q, wh, wl);
    prep_x_kernel<<<dim3(32, 32, 32), 256>>>(src_temp, src_search, xh, xl);

    // ---- convs on tensor cores (mma.sync bf16, 3-way split) ----
    dim3 gconv(HW / 128, 6, BB);
    conv_mma_kernel<<<gconv, 256, CONV_SMEM>>>(
        xh, xl, wh, wl, bk_m, bv_m, mkey, mval, CV * HW, 0);
    conv_mma_kernel<<<gconv, 256, CONV_SMEM>>>(
        xh + (size_t)BB * HW * CIN, xl + (size_t)BB * HW * CIN, wh, wl,
        bk_q, bv_q, qkey, out + (size_t)CV * HW, 1024 * HW, 768);

    // ---- attention (SIMT) ----
    dim3 gsc(HW / 128, HW / 128, BB);
    scores_kernel<<<gsc, 256>>>(qkey, mkey, scores);
    softmax_kernel<<<BB * HW, 256>>>(scores);
    dim3 gov(HW / 128, CV / 128, BB);
    outv_kernel<<<gov, 256>>>(mval, scores, out);
}